// round 1
// baseline (speedup 1.0000x reference)
#include <cuda_runtime.h>

// ForwardKinematicsAxis: G=131072 graphs, N=25 nodes, fixed heap tree p[i]=(i-1)/2.
// One thread per graph; DFS full unroll keeps only the ancestor path live in regs.

#define NN 25

// ---------- per-node local rotation ----------
struct LocalMat {
    float l[9];   // local = EulerXYZ(rpy) @ Rodrigues(theta, axis_raw)
    float o[3];   // xyz offset
};

template<int I>
__device__ __forceinline__ LocalMat compute_local(
    const float* __restrict__ x,
    const float* __restrict__ off,
    const float4* __restrict__ s_ax,
    int base)
{
    const int idx = base + I;
    const float4 ax = s_ax[I];
    const float th = x[idx] * ax.w;

    // offset row: 6 floats, 24B-aligned -> three float2 loads
    const float2* o2 = reinterpret_cast<const float2*>(off) + (size_t)idx * 3;
    const float2 oa = o2[0];
    const float2 ob = o2[1];
    const float2 oc = o2[2];
    const float ox = oa.x, oy = oa.y, oz = ob.x;
    const float a_r = ob.y;   // rpy[0] -> Rx
    const float a_p = oc.x;   // rpy[1] -> Ry
    const float a_y = oc.y;   // rpy[2] -> Rz

    float sx, cx, sy, cy, sz, cz, st, ct;
    __sincosf(a_r, &sx, &cx);
    __sincosf(a_p, &sy, &cy);
    __sincosf(a_y, &sz, &cz);
    __sincosf(th,  &st, &ct);

    // E = Rz @ Ry @ Rx
    const float e00 = cz * cy;
    const float e10 = sz * cy;
    const float e20 = -sy;
    const float e01 = cz * sy * sx - sz * cx;
    const float e11 = sz * sy * sx + cz * cx;
    const float e21 = cy * sx;
    const float e02 = cz * sy * cx + sz * sx;
    const float e12 = sz * sy * cx - cz * sx;
    const float e22 = cy * cx;

    // Rodrigues with RAW axis (reference does not normalize n)
    const float v  = 1.0f - ct;
    const float n1 = ax.x, n2 = ax.y, n3 = ax.z;
    const float n12v = n1 * n2 * v;
    const float n13v = n1 * n3 * v;
    const float n23v = n2 * n3 * v;
    const float r00 = ct + n1 * n1 * v;
    const float r01 = n12v - n3 * st;
    const float r02 = n13v + n2 * st;
    const float r10 = n12v + n3 * st;
    const float r11 = ct + n2 * n2 * v;
    const float r12 = n23v - n1 * st;
    const float r20 = n13v - n2 * st;
    const float r21 = n23v + n1 * st;
    const float r22 = ct + n3 * n3 * v;

    LocalMat L;
    L.l[0] = e00 * r00 + e01 * r10 + e02 * r20;
    L.l[1] = e00 * r01 + e01 * r11 + e02 * r21;
    L.l[2] = e00 * r02 + e01 * r12 + e02 * r22;
    L.l[3] = e10 * r00 + e11 * r10 + e12 * r20;
    L.l[4] = e10 * r01 + e11 * r11 + e12 * r21;
    L.l[5] = e10 * r02 + e11 * r12 + e12 * r22;
    L.l[6] = e20 * r00 + e21 * r10 + e22 * r20;
    L.l[7] = e20 * r01 + e21 * r11 + e22 * r21;
    L.l[8] = e20 * r02 + e21 * r12 + e22 * r22;
    L.o[0] = ox; L.o[1] = oy; L.o[2] = oz;
    return L;
}

__device__ __forceinline__ void store_node(
    float* __restrict__ out_pos, float* __restrict__ out_rot,
    float* __restrict__ out_gpos, int idx,
    const float (&R)[9], const float (&P)[3], const float (&Gp)[3])
{
    const int p3 = idx * 3;
    const int p9 = idx * 9;
    out_pos[p3 + 0] = P[0];  out_pos[p3 + 1] = P[1];  out_pos[p3 + 2] = P[2];
    out_gpos[p3 + 0] = Gp[0]; out_gpos[p3 + 1] = Gp[1]; out_gpos[p3 + 2] = Gp[2];
#pragma unroll
    for (int k = 0; k < 9; k++) out_rot[p9 + k] = R[k];
}

// DFS over tree; processes node I given parent's state, then recurses.
template<int I>
__device__ __forceinline__ void fk_node(
    const float* __restrict__ x, const float* __restrict__ off,
    const float4* __restrict__ s_ax,
    float* __restrict__ out_pos, float* __restrict__ out_rot,
    float* __restrict__ out_gpos, int base,
    const float (&pR)[9], const float (&pP)[3], const float (&pG)[3])
{
    const LocalMat L = compute_local<I>(x, off, s_ax, base);

    float R[9], P[3], Gp[3];
    // d = pR @ xyz
    const float d0 = pR[0] * L.o[0] + pR[1] * L.o[1] + pR[2] * L.o[2];
    const float d1 = pR[3] * L.o[0] + pR[4] * L.o[1] + pR[5] * L.o[2];
    const float d2 = pR[6] * L.o[0] + pR[7] * L.o[1] + pR[8] * L.o[2];
    P[0] = d0 + pP[0]; P[1] = d1 + pP[1]; P[2] = d2 + pP[2];
    Gp[0] = d0 + pG[0]; Gp[1] = d1 + pG[1]; Gp[2] = d2 + pG[2];
    // R = pR @ L
#pragma unroll
    for (int r = 0; r < 3; r++) {
#pragma unroll
        for (int c = 0; c < 3; c++) {
            R[r * 3 + c] = pR[r * 3 + 0] * L.l[0 * 3 + c]
                         + pR[r * 3 + 1] * L.l[1 * 3 + c]
                         + pR[r * 3 + 2] * L.l[2 * 3 + c];
        }
    }

    store_node(out_pos, out_rot, out_gpos, base + I, R, P, Gp);

    if constexpr (2 * I + 1 < NN)
        fk_node<2 * I + 1>(x, off, s_ax, out_pos, out_rot, out_gpos, base, R, P, Gp);
    if constexpr (2 * I + 2 < NN)
        fk_node<2 * I + 2>(x, off, s_ax, out_pos, out_rot, out_gpos, base, R, P, Gp);
}

__global__ void fk_kernel(
    const float* __restrict__ x,
    const float* __restrict__ off,
    const float* __restrict__ axis,
    float* __restrict__ out_pos,
    float* __restrict__ out_rot,
    float* __restrict__ out_gpos,
    int G)
{
    __shared__ float4 s_ax[NN];
    const int t = threadIdx.x;
    if (t < NN) {
        const float a0 = axis[t * 3 + 0];
        const float a1 = axis[t * 3 + 1];
        const float a2 = axis[t * 3 + 2];
        s_ax[t] = make_float4(a0, a1, a2, sqrtf(a0 * a0 + a1 * a1 + a2 * a2));
    }
    __syncthreads();

    const int g = blockIdx.x * blockDim.x + t;
    if (g >= G) return;
    const int base = g * NN;

    // Root node (node 0): pos = 0, gpos = xyz, rot = local
    const LocalMat L0 = compute_local<0>(x, off, s_ax, base);
    float R[9], P[3], Gp[3];
#pragma unroll
    for (int k = 0; k < 9; k++) R[k] = L0.l[k];
    P[0] = 0.f; P[1] = 0.f; P[2] = 0.f;
    Gp[0] = L0.o[0]; Gp[1] = L0.o[1]; Gp[2] = L0.o[2];
    store_node(out_pos, out_rot, out_gpos, base, R, P, Gp);

    fk_node<1>(x, off, s_ax, out_pos, out_rot, out_gpos, base, R, P, Gp);
    fk_node<2>(x, off, s_ax, out_pos, out_rot, out_gpos, base, R, P, Gp);
}

extern "C" void kernel_launch(void* const* d_in, const int* in_sizes, int n_in,
                              void* d_out, int out_size)
{
    // Locate inputs robustly by size (num_graphs scalar may or may not appear).
    // x: G*N floats, offset: 6*G*N floats, axis: 3*G*N floats.
    const float* x = (const float*)d_in[0];
    const int gn = in_sizes[0];           // G * 25
    const int G = gn / NN;

    const float* off = nullptr;
    const float* axis = nullptr;
    for (int i = 1; i < n_in; i++) {
        if (in_sizes[i] == 6 * gn) off = (const float*)d_in[i];
        else if (in_sizes[i] == 3 * gn && axis == nullptr) axis = (const float*)d_in[i];
    }

    float* out = (float*)d_out;
    float* out_pos  = out;                    // G*N*3
    float* out_rot  = out + (size_t)gn * 3;   // G*N*9
    float* out_gpos = out + (size_t)gn * 12;  // G*N*3
    (void)out_size;

    const int threads = 128;
    const int blocks = (G + threads - 1) / threads;
    fk_kernel<<<blocks, threads>>>(x, off, axis, out_pos, out_rot, out_gpos, G);
}

// round 2
// speedup vs baseline: 2.2986x; 2.2986x over previous
#include <cuda_runtime.h>

#define NN       25
#define GPB      128        // graphs per block (== threads)
#define THREADS  128
#define GPW      32         // graphs per warp
#define SLOT_F   15         // floats per node state: pos3 | gpos3 | rot9
#define NSLOTS   13
#define GSTRIDE  (NSLOTS * SLOT_F)   // 195 floats per graph in slab (odd -> conflict-free)
#define OFF_F    150        // 25 nodes * 6 floats
#define X_F      25
#define SMEM_FLOATS (GPB*OFF_F + GPB*X_F + GPB*GSTRIDE)   // 19200+3200+24960 = 47360
#define SMEM_BYTES  (SMEM_FLOATS * 4)                      // 189440

// ----- per-node compute: reads staged smem input + parent slab state, writes own slot -----
template<int I>
__device__ __forceinline__ void do_node(
    const float* __restrict__ s_off_t,   // this thread's 150-float offset row base
    const float* __restrict__ s_x_t,     // this thread's 25-float x base
    const float4* __restrict__ s_ax,
    float* __restrict__ slab_t)          // this thread's slab base (stride GSTRIDE across lanes)
{
    constexpr int SLOT = (I <= 12) ? I : ((I - 13) % 6);

    const float4 ax = s_ax[I];
    const float th = s_x_t[I] * ax.w;
    const float ox  = s_off_t[I*6+0];
    const float oy  = s_off_t[I*6+1];
    const float oz  = s_off_t[I*6+2];
    const float a_r = s_off_t[I*6+3];
    const float a_p = s_off_t[I*6+4];
    const float a_y = s_off_t[I*6+5];

    float sx, cx, sy, cy, sz, cz, st, ct;
    __sincosf(a_r, &sx, &cx);
    __sincosf(a_p, &sy, &cy);
    __sincosf(a_y, &sz, &cz);
    __sincosf(th,  &st, &ct);

    // E = Rz @ Ry @ Rx
    const float e00 = cz*cy,            e10 = sz*cy,            e20 = -sy;
    const float e01 = cz*sy*sx - sz*cx, e11 = sz*sy*sx + cz*cx, e21 = cy*sx;
    const float e02 = cz*sy*cx + sz*sx, e12 = sz*sy*cx - cz*sx, e22 = cy*cx;

    // Rodrigues with RAW axis
    const float v = 1.0f - ct, n1 = ax.x, n2 = ax.y, n3 = ax.z;
    const float n12v = n1*n2*v, n13v = n1*n3*v, n23v = n2*n3*v;
    const float r00 = ct + n1*n1*v, r01 = n12v - n3*st, r02 = n13v + n2*st;
    const float r10 = n12v + n3*st, r11 = ct + n2*n2*v, r12 = n23v - n1*st;
    const float r20 = n13v - n2*st, r21 = n23v + n1*st, r22 = ct + n3*n3*v;

    float L[9];
    L[0]=e00*r00+e01*r10+e02*r20; L[1]=e00*r01+e01*r11+e02*r21; L[2]=e00*r02+e01*r12+e02*r22;
    L[3]=e10*r00+e11*r10+e12*r20; L[4]=e10*r01+e11*r11+e12*r21; L[5]=e10*r02+e11*r12+e12*r22;
    L[6]=e20*r00+e21*r10+e22*r20; L[7]=e20*r01+e21*r11+e22*r21; L[8]=e20*r02+e21*r12+e22*r22;

    float* dst = slab_t + SLOT * SLOT_F;
    if constexpr (I == 0) {
        dst[0] = 0.f; dst[1] = 0.f; dst[2] = 0.f;
        dst[3] = ox;  dst[4] = oy;  dst[5] = oz;
        #pragma unroll
        for (int k = 0; k < 9; k++) dst[6+k] = L[k];
    } else {
        constexpr int P = (I - 1) / 2;    // parent node == parent slot (P <= 11, preserved)
        const float* ps = slab_t + P * SLOT_F;
        const float pP0 = ps[0], pP1 = ps[1], pP2 = ps[2];
        const float pG0 = ps[3], pG1 = ps[4], pG2 = ps[5];
        float pR[9];
        #pragma unroll
        for (int k = 0; k < 9; k++) pR[k] = ps[6+k];

        const float d0 = pR[0]*ox + pR[1]*oy + pR[2]*oz;
        const float d1 = pR[3]*ox + pR[4]*oy + pR[5]*oz;
        const float d2 = pR[6]*ox + pR[7]*oy + pR[8]*oz;
        dst[0] = d0 + pP0; dst[1] = d1 + pP1; dst[2] = d2 + pP2;
        dst[3] = d0 + pG0; dst[4] = d1 + pG1; dst[5] = d2 + pG2;
        #pragma unroll
        for (int r = 0; r < 3; r++)
            #pragma unroll
            for (int c = 0; c < 3; c++)
                dst[6 + r*3 + c] = pR[r*3+0]*L[c] + pR[r*3+1]*L[3+c] + pR[r*3+2]*L[6+c];
    }
}

// ----- coalesced per-warp flush of one output class for a contiguous node chunk -----
// dst is pre-offset to (warp's first graph, first node of chunk) in the output array.
template<int NNODES, int CLS_OFF, int CLS_F, int OUT_STRIDE>
__device__ __forceinline__ void flush_cls(
    float* __restrict__ dst, const float* __restrict__ slabW, int lane)
{
    constexpr int PERG = NNODES * CLS_F;
    constexpr int TOT  = GPW * PERG;
    #pragma unroll 4
    for (int idx = lane; idx < TOT; idx += 32) {
        const int g = idx / PERG;
        const int r = idx - g * PERG;
        const int n = r / CLS_F;
        const int k = r - n * CLS_F;
        dst[(size_t)g * OUT_STRIDE + r] = slabW[g * GSTRIDE + n * SLOT_F + CLS_OFF + k];
    }
}

__global__ void __launch_bounds__(THREADS, 1)
fk_kernel(const float* __restrict__ x,
          const float* __restrict__ off,
          const float* __restrict__ axis,
          float* __restrict__ out_pos,
          float* __restrict__ out_rot,
          float* __restrict__ out_gpos)
{
    extern __shared__ float sm[];
    float* s_off = sm;                          // GPB*150
    float* s_x   = sm + GPB * OFF_F;            // GPB*25
    float* slab  = s_x + GPB * X_F;             // GPB*195
    __shared__ float4 s_ax[NN];

    const int t = threadIdx.x;
    if (t < NN) {
        const float a0 = axis[t*3+0], a1 = axis[t*3+1], a2 = axis[t*3+2];
        s_ax[t] = make_float4(a0, a1, a2, sqrtf(a0*a0 + a1*a1 + a2*a2));
    }

    // Coalesced float4 staging of this block's input slabs
    {
        const float4* so = (const float4*)(off + (size_t)blockIdx.x * (GPB * OFF_F));
        float4* d = (float4*)s_off;
        #pragma unroll 4
        for (int i = t; i < GPB * OFF_F / 4; i += THREADS) d[i] = so[i];
        const float4* sx4 = (const float4*)(x + (size_t)blockIdx.x * (GPB * X_F));
        float4* dx = (float4*)s_x;
        #pragma unroll
        for (int i = t; i < GPB * X_F / 4; i += THREADS) dx[i] = sx4[i];
    }
    __syncthreads();

    const int lane = t & 31, w = t >> 5;
    float* slabW  = slab + w * (GPW * GSTRIDE);
    float* slab_t = slabW + lane * GSTRIDE;
    const float* s_off_t = s_off + t * OFF_F;
    const float* s_x_t   = s_x + t * X_F;
    const size_t gw0 = (size_t)blockIdx.x * GPB + w * GPW;

    // ---- chunk A: nodes 0..12 (slots 0..12) ----
    do_node<0>(s_off_t, s_x_t, s_ax, slab_t);
    do_node<1>(s_off_t, s_x_t, s_ax, slab_t);
    do_node<2>(s_off_t, s_x_t, s_ax, slab_t);
    do_node<3>(s_off_t, s_x_t, s_ax, slab_t);
    do_node<4>(s_off_t, s_x_t, s_ax, slab_t);
    do_node<5>(s_off_t, s_x_t, s_ax, slab_t);
    do_node<6>(s_off_t, s_x_t, s_ax, slab_t);
    do_node<7>(s_off_t, s_x_t, s_ax, slab_t);
    do_node<8>(s_off_t, s_x_t, s_ax, slab_t);
    do_node<9>(s_off_t, s_x_t, s_ax, slab_t);
    do_node<10>(s_off_t, s_x_t, s_ax, slab_t);
    do_node<11>(s_off_t, s_x_t, s_ax, slab_t);
    do_node<12>(s_off_t, s_x_t, s_ax, slab_t);
    __syncwarp();
    flush_cls<13, 0, 3,  75>(out_pos  + gw0 * 75,        slabW, lane);
    flush_cls<13, 3, 3,  75>(out_gpos + gw0 * 75,        slabW, lane);
    flush_cls<13, 6, 9, 225>(out_rot  + gw0 * 225,       slabW, lane);
    __syncwarp();

    // ---- chunk B: nodes 13..18 (slots 0..5; parents 6..8 preserved) ----
    do_node<13>(s_off_t, s_x_t, s_ax, slab_t);
    do_node<14>(s_off_t, s_x_t, s_ax, slab_t);
    do_node<15>(s_off_t, s_x_t, s_ax, slab_t);
    do_node<16>(s_off_t, s_x_t, s_ax, slab_t);
    do_node<17>(s_off_t, s_x_t, s_ax, slab_t);
    do_node<18>(s_off_t, s_x_t, s_ax, slab_t);
    __syncwarp();
    flush_cls<6, 0, 3,  75>(out_pos  + gw0 * 75  + 39,   slabW, lane);
    flush_cls<6, 3, 3,  75>(out_gpos + gw0 * 75  + 39,   slabW, lane);
    flush_cls<6, 6, 9, 225>(out_rot  + gw0 * 225 + 117,  slabW, lane);
    __syncwarp();

    // ---- chunk C: nodes 19..24 (slots 0..5; parents 9..11 preserved) ----
    do_node<19>(s_off_t, s_x_t, s_ax, slab_t);
    do_node<20>(s_off_t, s_x_t, s_ax, slab_t);
    do_node<21>(s_off_t, s_x_t, s_ax, slab_t);
    do_node<22>(s_off_t, s_x_t, s_ax, slab_t);
    do_node<23>(s_off_t, s_x_t, s_ax, slab_t);
    do_node<24>(s_off_t, s_x_t, s_ax, slab_t);
    __syncwarp();
    flush_cls<6, 0, 3,  75>(out_pos  + gw0 * 75  + 57,   slabW, lane);
    flush_cls<6, 3, 3,  75>(out_gpos + gw0 * 75  + 57,   slabW, lane);
    flush_cls<6, 6, 9, 225>(out_rot  + gw0 * 225 + 171,  slabW, lane);
}

// ---------- naive tail kernel for G % GPB != 0 (not used for the bench shape) ----------
__global__ void fk_tail_kernel(const float* __restrict__ x,
                               const float* __restrict__ off,
                               const float* __restrict__ axis,
                               float* __restrict__ out_pos,
                               float* __restrict__ out_rot,
                               float* __restrict__ out_gpos,
                               int g0, int G)
{
    const int g = g0 + blockIdx.x * blockDim.x + threadIdx.x;
    if (g >= G) return;
    float R[NN][9], Ps[NN][3], Gs[NN][3];
    for (int i = 0; i < NN; i++) {
        const int idx = g * NN + i;
        const float a0 = axis[i*3+0], a1 = axis[i*3+1], a2 = axis[i*3+2];
        const float th = x[idx] * sqrtf(a0*a0 + a1*a1 + a2*a2);
        const float* o = off + (size_t)idx * 6;
        const float ox = o[0], oy = o[1], oz = o[2];
        float sx,cx,sy,cy,sz,cz,st,ct;
        __sincosf(o[3],&sx,&cx); __sincosf(o[4],&sy,&cy); __sincosf(o[5],&sz,&cz);
        __sincosf(th,&st,&ct);
        const float e00=cz*cy, e10=sz*cy, e20=-sy;
        const float e01=cz*sy*sx-sz*cx, e11=sz*sy*sx+cz*cx, e21=cy*sx;
        const float e02=cz*sy*cx+sz*sx, e12=sz*sy*cx-cz*sx, e22=cy*cx;
        const float v=1.f-ct;
        const float r00=ct+a0*a0*v, r01=a0*a1*v-a2*st, r02=a0*a2*v+a1*st;
        const float r10=a0*a1*v+a2*st, r11=ct+a1*a1*v, r12=a1*a2*v-a0*st;
        const float r20=a0*a2*v-a1*st, r21=a1*a2*v+a0*st, r22=ct+a2*a2*v;
        float L[9];
        L[0]=e00*r00+e01*r10+e02*r20; L[1]=e00*r01+e01*r11+e02*r21; L[2]=e00*r02+e01*r12+e02*r22;
        L[3]=e10*r00+e11*r10+e12*r20; L[4]=e10*r01+e11*r11+e12*r21; L[5]=e10*r02+e11*r12+e12*r22;
        L[6]=e20*r00+e21*r10+e22*r20; L[7]=e20*r01+e21*r11+e22*r21; L[8]=e20*r02+e21*r12+e22*r22;
        if (i == 0) {
            Ps[0][0]=Ps[0][1]=Ps[0][2]=0.f;
            Gs[0][0]=ox; Gs[0][1]=oy; Gs[0][2]=oz;
            for (int k=0;k<9;k++) R[0][k]=L[k];
        } else {
            const int p = (i-1)/2;
            const float d0=R[p][0]*ox+R[p][1]*oy+R[p][2]*oz;
            const float d1=R[p][3]*ox+R[p][4]*oy+R[p][5]*oz;
            const float d2=R[p][6]*ox+R[p][7]*oy+R[p][8]*oz;
            Ps[i][0]=d0+Ps[p][0]; Ps[i][1]=d1+Ps[p][1]; Ps[i][2]=d2+Ps[p][2];
            Gs[i][0]=d0+Gs[p][0]; Gs[i][1]=d1+Gs[p][1]; Gs[i][2]=d2+Gs[p][2];
            for (int r=0;r<3;r++) for (int c=0;c<3;c++)
                R[i][r*3+c]=R[p][r*3+0]*L[c]+R[p][r*3+1]*L[3+c]+R[p][r*3+2]*L[6+c];
        }
        const int p3=(g*NN+i)*3, p9=(g*NN+i)*9;
        out_pos[p3+0]=Ps[i][0]; out_pos[p3+1]=Ps[i][1]; out_pos[p3+2]=Ps[i][2];
        out_gpos[p3+0]=Gs[i][0]; out_gpos[p3+1]=Gs[i][1]; out_gpos[p3+2]=Gs[i][2];
        for (int k=0;k<9;k++) out_rot[p9+k]=R[i][k];
    }
}

extern "C" void kernel_launch(void* const* d_in, const int* in_sizes, int n_in,
                              void* d_out, int out_size)
{
    const float* x = (const float*)d_in[0];
    const int gn = in_sizes[0];          // G * 25
    const int G  = gn / NN;

    const float* off = nullptr;
    const float* axis = nullptr;
    for (int i = 1; i < n_in; i++) {
        if (in_sizes[i] == 6 * gn) off = (const float*)d_in[i];
        else if (in_sizes[i] == 3 * gn && axis == nullptr) axis = (const float*)d_in[i];
    }

    float* out = (float*)d_out;
    float* out_pos  = out;                    // G*N*3
    float* out_rot  = out + (size_t)gn * 3;   // G*N*9
    float* out_gpos = out + (size_t)gn * 12;  // G*N*3
    (void)out_size;

    static bool attr_set = false;
    if (!attr_set) {
        cudaFuncSetAttribute(fk_kernel, cudaFuncAttributeMaxDynamicSharedMemorySize, SMEM_BYTES);
        attr_set = true;
    }

    const int full_blocks = G / GPB;
    if (full_blocks > 0)
        fk_kernel<<<full_blocks, THREADS, SMEM_BYTES>>>(x, off, axis, out_pos, out_rot, out_gpos);
    const int rem = G - full_blocks * GPB;
    if (rem > 0) {
        const int tb = 128;
        fk_tail_kernel<<<(rem + tb - 1) / tb, tb>>>(x, off, axis, out_pos, out_rot, out_gpos,
                                                    full_blocks * GPB, G);
    }
}

// round 3
// speedup vs baseline: 3.3847x; 1.4725x over previous
#include <cuda_runtime.h>

#define NN      25
#define THREADS 128
#define GPW     32
#define GPB     128
#define SXF     (GPW * NN)          // 800  : staged x, [g][25], stride 25
#define SINF    (GPW * 31)          // 992  : staged offset chunk, [g][31] (30 used)
#define SOUTF   (GPW * 75)          // 2400 : staged outputs, [g][ pos15 | gpos15 | rot45 ]
#define WARP_F  (SXF + SINF + SOUTF)            // 4192 floats
#define SMEM_BYTES ((THREADS/32) * WARP_F * 4)  // 67072 B -> 3 blocks/SM

// ---------------- per-node compute: staged smem in, register states, staged smem out ----
template<int I, int N0>
__device__ __forceinline__ void proc_node(
    const float* __restrict__ s_in_t,   // lane base, stride 31 across lanes
    const float* __restrict__ s_x_t,    // lane base, stride 25
    const float4* __restrict__ s_ax,
    float* __restrict__ s_out_t,        // lane base, stride 75
    float (&stR)[12][9], float (&stP)[12][3],
    float& rx, float& ry, float& rz)
{
    constexpr int J = I - N0;
    const float4 ax = s_ax[I];
    const float th = s_x_t[I] * ax.w;
    const float ox = s_in_t[J*6+0], oy = s_in_t[J*6+1], oz = s_in_t[J*6+2];

    float sx,cx,sy,cy,sz,cz,st,ct;
    __sincosf(s_in_t[J*6+3], &sx, &cx);
    __sincosf(s_in_t[J*6+4], &sy, &cy);
    __sincosf(s_in_t[J*6+5], &sz, &cz);
    __sincosf(th, &st, &ct);

    // E = Rz @ Ry @ Rx
    const float e00=cz*cy,            e10=sz*cy,            e20=-sy;
    const float e01=cz*sy*sx - sz*cx, e11=sz*sy*sx + cz*cx, e21=cy*sx;
    const float e02=cz*sy*cx + sz*sx, e12=sz*sy*cx - cz*sx, e22=cy*cx;

    // Rodrigues with RAW axis
    const float v=1.f-ct, n1=ax.x, n2=ax.y, n3=ax.z;
    const float n12v=n1*n2*v, n13v=n1*n3*v, n23v=n2*n3*v;
    const float r00=ct+n1*n1*v, r01=n12v-n3*st, r02=n13v+n2*st;
    const float r10=n12v+n3*st, r11=ct+n2*n2*v, r12=n23v-n1*st;
    const float r20=n13v-n2*st, r21=n23v+n1*st, r22=ct+n3*n3*v;

    float L[9];
    L[0]=e00*r00+e01*r10+e02*r20; L[1]=e00*r01+e01*r11+e02*r21; L[2]=e00*r02+e01*r12+e02*r22;
    L[3]=e10*r00+e11*r10+e12*r20; L[4]=e10*r01+e11*r11+e12*r21; L[5]=e10*r02+e11*r12+e12*r22;
    L[6]=e20*r00+e21*r10+e22*r20; L[7]=e20*r01+e21*r11+e22*r21; L[8]=e20*r02+e21*r12+e22*r22;

    float R[9], P[3];
    if constexpr (I == 0) {
        #pragma unroll
        for (int k=0;k<9;k++) R[k]=L[k];
        P[0]=0.f; P[1]=0.f; P[2]=0.f;
        rx=ox; ry=oy; rz=oz;                 // gpos = pos + root xyz (induction)
    } else {
        constexpr int Par = (I-1)/2;
        const float d0 = stR[Par][0]*ox + stR[Par][1]*oy + stR[Par][2]*oz;
        const float d1 = stR[Par][3]*ox + stR[Par][4]*oy + stR[Par][5]*oz;
        const float d2 = stR[Par][6]*ox + stR[Par][7]*oy + stR[Par][8]*oz;
        P[0]=d0+stP[Par][0]; P[1]=d1+stP[Par][1]; P[2]=d2+stP[Par][2];
        #pragma unroll
        for (int r=0;r<3;r++)
            #pragma unroll
            for (int c=0;c<3;c++)
                R[r*3+c]=stR[Par][r*3+0]*L[c]+stR[Par][r*3+1]*L[3+c]+stR[Par][r*3+2]*L[6+c];
    }

    // stage outputs: pos | gpos | rot
    s_out_t[J*3+0]=P[0]; s_out_t[J*3+1]=P[1]; s_out_t[J*3+2]=P[2];
    s_out_t[15+J*3+0]=P[0]+rx; s_out_t[15+J*3+1]=P[1]+ry; s_out_t[15+J*3+2]=P[2]+rz;
    #pragma unroll
    for (int k=0;k<9;k++) s_out_t[30+J*9+k]=R[k];

    if constexpr (I < 12) {           // nodes >= 12 have no children in range
        #pragma unroll
        for (int k=0;k<9;k++) stR[I][k]=R[k];
        stP[I][0]=P[0]; stP[I][1]=P[1]; stP[I][2]=P[2];
    }
}

// ---------------- one 5-node chunk: stage inputs -> compute -> coalesced flush ----------
template<int N0>
__device__ __forceinline__ void run_chunk(
    const float* __restrict__ off, size_t gw0, int lane,
    float* __restrict__ s_in, const float* __restrict__ s_in_t,
    const float* __restrict__ s_x_t, const float4* __restrict__ s_ax,
    float* __restrict__ s_out, float* __restrict__ s_out_t,
    float* __restrict__ out_pos, float* __restrict__ out_rot, float* __restrict__ out_gpos,
    float (&stR)[12][9], float (&stP)[12][3], float& rx, float& ry, float& rz)
{
    // stage: 32 graphs x 30 floats, coalesced LDG (contiguous 120B per graph)
    if (lane < 30) {
        const float* src = off + gw0*150 + N0*6 + lane;
        float* dst = s_in + lane;
        #pragma unroll 8
        for (int g = 0; g < GPW; g++)
            dst[g*31] = src[(size_t)g*150];
    }
    __syncwarp();

    proc_node<N0+0,N0>(s_in_t, s_x_t, s_ax, s_out_t, stR, stP, rx,ry,rz);
    proc_node<N0+1,N0>(s_in_t, s_x_t, s_ax, s_out_t, stR, stP, rx,ry,rz);
    proc_node<N0+2,N0>(s_in_t, s_x_t, s_ax, s_out_t, stR, stP, rx,ry,rz);
    proc_node<N0+3,N0>(s_in_t, s_x_t, s_ax, s_out_t, stR, stP, rx,ry,rz);
    proc_node<N0+4,N0>(s_in_t, s_x_t, s_ax, s_out_t, stR, stP, rx,ry,rz);
    __syncwarp();

    // flush: graphs-outer, contiguous runs, pointer increments (no div/mod)
    {
        const float* s = s_out;
        float* dp = out_pos  + gw0*75  + N0*3;
        float* dg = out_gpos + gw0*75  + N0*3;
        float* dr = out_rot  + gw0*225 + N0*9;
        #pragma unroll 4
        for (int g = 0; g < GPW; g++) {
            if (lane < 15) {
                dp[lane] = s[lane];
                dg[lane] = s[15+lane];
            }
            dr[lane] = s[30+lane];
            if (lane < 13) dr[32+lane] = s[62+lane];
            s += 75; dp += 75; dg += 75; dr += 225;
        }
    }
    __syncwarp();   // WAR protection for s_in/s_out reuse next chunk
}

__global__ void __launch_bounds__(THREADS, 3)
fk_kernel(const float* __restrict__ x,
          const float* __restrict__ off,
          const float* __restrict__ axis,
          float* __restrict__ out_pos,
          float* __restrict__ out_rot,
          float* __restrict__ out_gpos)
{
    extern __shared__ float sm[];
    __shared__ float4 s_ax[NN];

    const int t = threadIdx.x;
    if (t < NN) {
        const float a0 = axis[t*3+0], a1 = axis[t*3+1], a2 = axis[t*3+2];
        s_ax[t] = make_float4(a0, a1, a2, sqrtf(a0*a0 + a1*a1 + a2*a2));
    }
    __syncthreads();

    const int lane = t & 31, w = t >> 5;
    float* s_warp = sm + w * WARP_F;
    float* s_x    = s_warp;              // [32][25] (naturally linear)
    float* s_in   = s_warp + SXF;        // [32][31]
    float* s_out  = s_warp + SXF + SINF; // [32][75]

    const size_t gw0 = (size_t)blockIdx.x * GPB + (size_t)w * GPW;

    // stage x once: 800 contiguous floats, perfectly coalesced
    {
        const float* src = x + gw0 * NN;
        #pragma unroll 5
        for (int i = lane; i < SXF; i += 32) s_x[i] = src[i];
    }
    __syncwarp();

    const float* s_x_t  = s_x + lane * NN;
    const float* s_in_t = s_in + lane * 31;
    float*       s_out_t= s_out + lane * 75;

    float stR[12][9], stP[12][3];
    float rx = 0.f, ry = 0.f, rz = 0.f;

    run_chunk<0 >(off, gw0, lane, s_in, s_in_t, s_x_t, s_ax, s_out, s_out_t,
                  out_pos, out_rot, out_gpos, stR, stP, rx, ry, rz);
    run_chunk<5 >(off, gw0, lane, s_in, s_in_t, s_x_t, s_ax, s_out, s_out_t,
                  out_pos, out_rot, out_gpos, stR, stP, rx, ry, rz);
    run_chunk<10>(off, gw0, lane, s_in, s_in_t, s_x_t, s_ax, s_out, s_out_t,
                  out_pos, out_rot, out_gpos, stR, stP, rx, ry, rz);
    run_chunk<15>(off, gw0, lane, s_in, s_in_t, s_x_t, s_ax, s_out, s_out_t,
                  out_pos, out_rot, out_gpos, stR, stP, rx, ry, rz);
    run_chunk<20>(off, gw0, lane, s_in, s_in_t, s_x_t, s_ax, s_out, s_out_t,
                  out_pos, out_rot, out_gpos, stR, stP, rx, ry, rz);
}

// ---------- naive tail kernel for G % 128 != 0 (not used for the bench shape) ----------
__global__ void fk_tail_kernel(const float* __restrict__ x,
                               const float* __restrict__ off,
                               const float* __restrict__ axis,
                               float* __restrict__ out_pos,
                               float* __restrict__ out_rot,
                               float* __restrict__ out_gpos,
                               int g0, int G)
{
    const int g = g0 + blockIdx.x * blockDim.x + threadIdx.x;
    if (g >= G) return;
    float R[NN][9], Ps[NN][3], Gs[NN][3];
    for (int i = 0; i < NN; i++) {
        const int idx = g * NN + i;
        const float a0 = axis[i*3+0], a1 = axis[i*3+1], a2 = axis[i*3+2];
        const float th = x[idx] * sqrtf(a0*a0+a1*a1+a2*a2);
        const float* o = off + (size_t)idx * 6;
        const float ox=o[0], oy=o[1], oz=o[2];
        float sx,cx,sy,cy,sz,cz,st,ct;
        __sincosf(o[3],&sx,&cx); __sincosf(o[4],&sy,&cy); __sincosf(o[5],&sz,&cz);
        __sincosf(th,&st,&ct);
        const float e00=cz*cy, e10=sz*cy, e20=-sy;
        const float e01=cz*sy*sx-sz*cx, e11=sz*sy*sx+cz*cx, e21=cy*sx;
        const float e02=cz*sy*cx+sz*sx, e12=sz*sy*cx-cz*sx, e22=cy*cx;
        const float v=1.f-ct;
        const float r00=ct+a0*a0*v, r01=a0*a1*v-a2*st, r02=a0*a2*v+a1*st;
        const float r10=a0*a1*v+a2*st, r11=ct+a1*a1*v, r12=a1*a2*v-a0*st;
        const float r20=a0*a2*v-a1*st, r21=a1*a2*v+a0*st, r22=ct+a2*a2*v;
        float L[9];
        L[0]=e00*r00+e01*r10+e02*r20; L[1]=e00*r01+e01*r11+e02*r21; L[2]=e00*r02+e01*r12+e02*r22;
        L[3]=e10*r00+e11*r10+e12*r20; L[4]=e10*r01+e11*r11+e12*r21; L[5]=e10*r02+e11*r12+e12*r22;
        L[6]=e20*r00+e21*r10+e22*r20; L[7]=e20*r01+e21*r11+e22*r21; L[8]=e20*r02+e21*r12+e22*r22;
        if (i == 0) {
            Ps[0][0]=Ps[0][1]=Ps[0][2]=0.f;
            Gs[0][0]=ox; Gs[0][1]=oy; Gs[0][2]=oz;
            for (int k=0;k<9;k++) R[0][k]=L[k];
        } else {
            const int p=(i-1)/2;
            const float d0=R[p][0]*ox+R[p][1]*oy+R[p][2]*oz;
            const float d1=R[p][3]*ox+R[p][4]*oy+R[p][5]*oz;
            const float d2=R[p][6]*ox+R[p][7]*oy+R[p][8]*oz;
            Ps[i][0]=d0+Ps[p][0]; Ps[i][1]=d1+Ps[p][1]; Ps[i][2]=d2+Ps[p][2];
            Gs[i][0]=d0+Gs[p][0]; Gs[i][1]=d1+Gs[p][1]; Gs[i][2]=d2+Gs[p][2];
            for (int r=0;r<3;r++) for (int c=0;c<3;c++)
                R[i][r*3+c]=R[p][r*3+0]*L[c]+R[p][r*3+1]*L[3+c]+R[p][r*3+2]*L[6+c];
        }
        const int p3=idx*3, p9=idx*9;
        out_pos[p3+0]=Ps[i][0]; out_pos[p3+1]=Ps[i][1]; out_pos[p3+2]=Ps[i][2];
        out_gpos[p3+0]=Gs[i][0]; out_gpos[p3+1]=Gs[i][1]; out_gpos[p3+2]=Gs[i][2];
        for (int k=0;k<9;k++) out_rot[p9+k]=R[i][k];
    }
}

extern "C" void kernel_launch(void* const* d_in, const int* in_sizes, int n_in,
                              void* d_out, int out_size)
{
    const float* x = (const float*)d_in[0];
    const int gn = in_sizes[0];          // G * 25
    const int G  = gn / NN;

    const float* off = nullptr;
    const float* axis = nullptr;
    for (int i = 1; i < n_in; i++) {
        if (in_sizes[i] == 6 * gn) off = (const float*)d_in[i];
        else if (in_sizes[i] == 3 * gn && axis == nullptr) axis = (const float*)d_in[i];
    }

    float* out = (float*)d_out;
    float* out_pos  = out;                    // G*N*3
    float* out_rot  = out + (size_t)gn * 3;   // G*N*9
    float* out_gpos = out + (size_t)gn * 12;  // G*N*3
    (void)out_size;

    static bool attr_set = false;
    if (!attr_set) {
        cudaFuncSetAttribute(fk_kernel, cudaFuncAttributeMaxDynamicSharedMemorySize, SMEM_BYTES);
        attr_set = true;
    }

    const int full_blocks = G / GPB;
    if (full_blocks > 0)
        fk_kernel<<<full_blocks, THREADS, SMEM_BYTES>>>(x, off, axis, out_pos, out_rot, out_gpos);
    const int rem = G - full_blocks * GPB;
    if (rem > 0) {
        const int tb = 128;
        fk_tail_kernel<<<(rem + tb - 1) / tb, tb>>>(x, off, axis, out_pos, out_rot, out_gpos,
                                                    full_blocks * GPB, G);
    }
}

// round 5
// speedup vs baseline: 3.6165x; 1.0685x over previous
#include <cuda_runtime.h>

#define NN      25
#define THREADS 128
#define GPW     32
#define GPB     128
#define INW     35                   // staged row: 30 offset + 5 x (odd stride)
#define OUTW    75                   // staged out row: pos15 | gpos15 | rot45 (odd)
#define WARP_F  ((INW + OUTW) * GPW)            // 3520 floats
#define SMEM_BYTES ((THREADS/32) * WARP_F * 4)  // 56320 B -> 4 blocks/SM

// ---------------- per-node compute: staged smem in, register states, staged smem out ----
template<int I, int N0>
__device__ __forceinline__ void proc_node(
    const float* __restrict__ s_in_t,   // lane row base (stride INW across lanes)
    const float4* __restrict__ s_ax,
    float* __restrict__ s_out_t,        // lane row base (stride OUTW)
    float (&stR)[12][9], float (&stP)[12][3],
    float& rx, float& ry, float& rz)
{
    constexpr int J = I - N0;
    const float4 ax = s_ax[I];
    const float th = s_in_t[30 + J] * ax.w;
    const float ox = s_in_t[J*6+0], oy = s_in_t[J*6+1], oz = s_in_t[J*6+2];

    float sx,cx,sy,cy,sz,cz,st,ct;
    __sincosf(s_in_t[J*6+3], &sx, &cx);
    __sincosf(s_in_t[J*6+4], &sy, &cy);
    __sincosf(s_in_t[J*6+5], &sz, &cz);
    __sincosf(th, &st, &ct);

    // E = Rz @ Ry @ Rx
    const float e00=cz*cy,            e10=sz*cy,            e20=-sy;
    const float e01=cz*sy*sx - sz*cx, e11=sz*sy*sx + cz*cx, e21=cy*sx;
    const float e02=cz*sy*cx + sz*sx, e12=sz*sy*cx - cz*sx, e22=cy*cx;

    // Rodrigues with RAW axis
    const float v=1.f-ct, n1=ax.x, n2=ax.y, n3=ax.z;
    const float n12v=n1*n2*v, n13v=n1*n3*v, n23v=n2*n3*v;
    const float r00=ct+n1*n1*v, r01=n12v-n3*st, r02=n13v+n2*st;
    const float r10=n12v+n3*st, r11=ct+n2*n2*v, r12=n23v-n1*st;
    const float r20=n13v-n2*st, r21=n23v+n1*st, r22=ct+n3*n3*v;

    float L[9];
    L[0]=e00*r00+e01*r10+e02*r20; L[1]=e00*r01+e01*r11+e02*r21; L[2]=e00*r02+e01*r12+e02*r22;
    L[3]=e10*r00+e11*r10+e12*r20; L[4]=e10*r01+e11*r11+e12*r21; L[5]=e10*r02+e11*r12+e12*r22;
    L[6]=e20*r00+e21*r10+e22*r20; L[7]=e20*r01+e21*r11+e22*r21; L[8]=e20*r02+e21*r12+e22*r22;

    float R[9], P[3];
    if constexpr (I == 0) {
        #pragma unroll
        for (int k=0;k<9;k++) R[k]=L[k];
        P[0]=0.f; P[1]=0.f; P[2]=0.f;
        rx=ox; ry=oy; rz=oz;                 // gpos = pos + root xyz (induction)
    } else {
        constexpr int Par = (I-1)/2;
        const float d0 = stR[Par][0]*ox + stR[Par][1]*oy + stR[Par][2]*oz;
        const float d1 = stR[Par][3]*ox + stR[Par][4]*oy + stR[Par][5]*oz;
        const float d2 = stR[Par][6]*ox + stR[Par][7]*oy + stR[Par][8]*oz;
        P[0]=d0+stP[Par][0]; P[1]=d1+stP[Par][1]; P[2]=d2+stP[Par][2];
        #pragma unroll
        for (int r=0;r<3;r++)
            #pragma unroll
            for (int c=0;c<3;c++)
                R[r*3+c]=stR[Par][r*3+0]*L[c]+stR[Par][r*3+1]*L[3+c]+stR[Par][r*3+2]*L[6+c];
    }

    // stage outputs: pos | gpos | rot
    s_out_t[J*3+0]=P[0]; s_out_t[J*3+1]=P[1]; s_out_t[J*3+2]=P[2];
    s_out_t[15+J*3+0]=P[0]+rx; s_out_t[15+J*3+1]=P[1]+ry; s_out_t[15+J*3+2]=P[2]+rz;
    #pragma unroll
    for (int k=0;k<9;k++) s_out_t[30+J*9+k]=R[k];

    if constexpr (I < 12) {           // nodes >= 12 have no children
        #pragma unroll
        for (int k=0;k<9;k++) stR[I][k]=R[k];
        stP[I][0]=P[0]; stP[I][1]=P[1]; stP[I][2]=P[2];
    }
}

// ---------------- one 5-node chunk: stage inputs -> compute -> coalesced flush ----------
template<int N0>
__device__ __forceinline__ void run_chunk(
    const float* __restrict__ x, const float* __restrict__ off, size_t gw0, int lane,
    float* __restrict__ s_in, const float* __restrict__ s_in_t,
    const float4* __restrict__ s_ax,
    float* __restrict__ s_out, float* __restrict__ s_out_t,
    float* __restrict__ out_pos, float* __restrict__ out_rot, float* __restrict__ out_gpos,
    float (&stR)[12][9], float (&stP)[12][3], float& rx, float& ry, float& rz)
{
    // stage offsets: 32 graphs x 30 floats, lanes 0..29 active (contiguous 120B per graph)
    if (lane < 30) {
        const float* srcO = off + gw0*150 + N0*6 + lane;
        float* dst = s_in + lane;
        #pragma unroll 8
        for (int g = 0; g < GPW; g++)
            dst[g*INW] = srcO[(size_t)g*150];
    }
    // stage x: 32 graphs x 5 floats, flat-indexed across all 32 lanes (FIX for R4 bug)
    {
        const float* xb = x + gw0*25 + N0;
        int idx = lane;
        #pragma unroll
        for (int it = 0; it < 5; it++) {       // 32*5 = 160 elements
            const int g = idx / 5;
            const int j = idx - g * 5;
            s_in[g*INW + 30 + j] = xb[(size_t)g*25 + j];
            idx += 32;
        }
    }
    __syncwarp();

    proc_node<N0+0,N0>(s_in_t, s_ax, s_out_t, stR, stP, rx,ry,rz);
    proc_node<N0+1,N0>(s_in_t, s_ax, s_out_t, stR, stP, rx,ry,rz);
    proc_node<N0+2,N0>(s_in_t, s_ax, s_out_t, stR, stP, rx,ry,rz);
    proc_node<N0+3,N0>(s_in_t, s_ax, s_out_t, stR, stP, rx,ry,rz);
    proc_node<N0+4,N0>(s_in_t, s_ax, s_out_t, stR, stP, rx,ry,rz);
    __syncwarp();

    // flush: graphs-outer, contiguous runs, pointer increments (no div/mod)
    {
        const float* s = s_out;
        float* dp = out_pos  + gw0*75  + N0*3;
        float* dg = out_gpos + gw0*75  + N0*3;
        float* dr = out_rot  + gw0*225 + N0*9;
        #pragma unroll 8
        for (int g = 0; g < GPW; g++) {
            if (lane < 15) {
                dp[lane] = s[lane];
                dg[lane] = s[15+lane];
            }
            dr[lane] = s[30+lane];
            if (lane < 13) dr[32+lane] = s[62+lane];
            s += OUTW; dp += 75; dg += 75; dr += 225;
        }
    }
    __syncwarp();   // WAR protection before s_in/s_out reuse
}

__global__ void __launch_bounds__(THREADS, 4)
fk_kernel(const float* __restrict__ x,
          const float* __restrict__ off,
          const float* __restrict__ axis,
          float* __restrict__ out_pos,
          float* __restrict__ out_rot,
          float* __restrict__ out_gpos)
{
    extern __shared__ float sm[];
    __shared__ float4 s_ax[NN];

    const int t = threadIdx.x;
    if (t < NN) {
        const float a0 = axis[t*3+0], a1 = axis[t*3+1], a2 = axis[t*3+2];
        s_ax[t] = make_float4(a0, a1, a2, sqrtf(a0*a0 + a1*a1 + a2*a2));
    }
    __syncthreads();

    const int lane = t & 31, w = t >> 5;
    float* s_warp = sm + w * WARP_F;
    float* s_in   = s_warp;                 // [32][35]
    float* s_out  = s_warp + GPW * INW;     // [32][75]

    const size_t gw0 = (size_t)blockIdx.x * GPB + (size_t)w * GPW;

    const float* s_in_t  = s_in  + lane * INW;
    float*       s_out_t = s_out + lane * OUTW;

    float stR[12][9], stP[12][3];
    float rx = 0.f, ry = 0.f, rz = 0.f;

    run_chunk<0 >(x, off, gw0, lane, s_in, s_in_t, s_ax, s_out, s_out_t,
                  out_pos, out_rot, out_gpos, stR, stP, rx, ry, rz);
    run_chunk<5 >(x, off, gw0, lane, s_in, s_in_t, s_ax, s_out, s_out_t,
                  out_pos, out_rot, out_gpos, stR, stP, rx, ry, rz);
    run_chunk<10>(x, off, gw0, lane, s_in, s_in_t, s_ax, s_out, s_out_t,
                  out_pos, out_rot, out_gpos, stR, stP, rx, ry, rz);
    run_chunk<15>(x, off, gw0, lane, s_in, s_in_t, s_ax, s_out, s_out_t,
                  out_pos, out_rot, out_gpos, stR, stP, rx, ry, rz);
    run_chunk<20>(x, off, gw0, lane, s_in, s_in_t, s_ax, s_out, s_out_t,
                  out_pos, out_rot, out_gpos, stR, stP, rx, ry, rz);
}

// ---------- naive tail kernel for G % 128 != 0 (not used for the bench shape) ----------
__global__ void fk_tail_kernel(const float* __restrict__ x,
                               const float* __restrict__ off,
                               const float* __restrict__ axis,
                               float* __restrict__ out_pos,
                               float* __restrict__ out_rot,
                               float* __restrict__ out_gpos,
                               int g0, int G)
{
    const int g = g0 + blockIdx.x * blockDim.x + threadIdx.x;
    if (g >= G) return;
    float R[NN][9], Ps[NN][3], Gs[NN][3];
    for (int i = 0; i < NN; i++) {
        const int idx = g * NN + i;
        const float a0 = axis[i*3+0], a1 = axis[i*3+1], a2 = axis[i*3+2];
        const float th = x[idx] * sqrtf(a0*a0+a1*a1+a2*a2);
        const float* o = off + (size_t)idx * 6;
        const float ox=o[0], oy=o[1], oz=o[2];
        float sx,cx,sy,cy,sz,cz,st,ct;
        __sincosf(o[3],&sx,&cx); __sincosf(o[4],&sy,&cy); __sincosf(o[5],&sz,&cz);
        __sincosf(th,&st,&ct);
        const float e00=cz*cy, e10=sz*cy, e20=-sy;
        const float e01=cz*sy*sx-sz*cx, e11=sz*sy*sx+cz*cx, e21=cy*sx;
        const float e02=cz*sy*cx+sz*sx, e12=sz*sy*cx-cz*sx, e22=cy*cx;
        const float v=1.f-ct;
        const float r00=ct+a0*a0*v, r01=a0*a1*v-a2*st, r02=a0*a2*v+a1*st;
        const float r10=a0*a1*v+a2*st, r11=ct+a1*a1*v, r12=a1*a2*v-a0*st;
        const float r20=a0*a2*v-a1*st, r21=a1*a2*v+a0*st, r22=ct+a2*a2*v;
        float L[9];
        L[0]=e00*r00+e01*r10+e02*r20; L[1]=e00*r01+e01*r11+e02*r21; L[2]=e00*r02+e01*r12+e02*r22;
        L[3]=e10*r00+e11*r10+e12*r20; L[4]=e10*r01+e11*r11+e12*r21; L[5]=e10*r02+e11*r12+e12*r22;
        L[6]=e20*r00+e21*r10+e22*r20; L[7]=e20*r01+e21*r11+e22*r21; L[8]=e20*r02+e21*r12+e22*r22;
        if (i == 0) {
            Ps[0][0]=Ps[0][1]=Ps[0][2]=0.f;
            Gs[0][0]=ox; Gs[0][1]=oy; Gs[0][2]=oz;
            for (int k=0;k<9;k++) R[0][k]=L[k];
        } else {
            const int p=(i-1)/2;
            const float d0=R[p][0]*ox+R[p][1]*oy+R[p][2]*oz;
            const float d1=R[p][3]*ox+R[p][4]*oy+R[p][5]*oz;
            const float d2=R[p][6]*ox+R[p][7]*oy+R[p][8]*oz;
            Ps[i][0]=d0+Ps[p][0]; Ps[i][1]=d1+Ps[p][1]; Ps[i][2]=d2+Ps[p][2];
            Gs[i][0]=d0+Gs[p][0]; Gs[i][1]=d1+Gs[p][1]; Gs[i][2]=d2+Gs[p][2];
            for (int r=0;r<3;r++) for (int c=0;c<3;c++)
                R[i][r*3+c]=R[p][r*3+0]*L[c]+R[p][r*3+1]*L[3+c]+R[p][r*3+2]*L[6+c];
        }
        const int p3=idx*3, p9=idx*9;
        out_pos[p3+0]=Ps[i][0]; out_pos[p3+1]=Ps[i][1]; out_pos[p3+2]=Ps[i][2];
        out_gpos[p3+0]=Gs[i][0]; out_gpos[p3+1]=Gs[i][1]; out_gpos[p3+2]=Gs[i][2];
        for (int k=0;k<9;k++) out_rot[p9+k]=R[i][k];
    }
}

extern "C" void kernel_launch(void* const* d_in, const int* in_sizes, int n_in,
                              void* d_out, int out_size)
{
    const float* x = (const float*)d_in[0];
    const int gn = in_sizes[0];          // G * 25
    const int G  = gn / NN;

    const float* off = nullptr;
    const float* axis = nullptr;
    for (int i = 1; i < n_in; i++) {
        if (in_sizes[i] == 6 * gn) off = (const float*)d_in[i];
        else if (in_sizes[i] == 3 * gn && axis == nullptr) axis = (const float*)d_in[i];
    }

    float* out = (float*)d_out;
    float* out_pos  = out;                    // G*N*3
    float* out_rot  = out + (size_t)gn * 3;   // G*N*9
    float* out_gpos = out + (size_t)gn * 12;  // G*N*3
    (void)out_size;

    static bool attr_set = false;
    if (!attr_set) {
        cudaFuncSetAttribute(fk_kernel, cudaFuncAttributeMaxDynamicSharedMemorySize, SMEM_BYTES);
        attr_set = true;
    }

    const int full_blocks = G / GPB;
    if (full_blocks > 0)
        fk_kernel<<<full_blocks, THREADS, SMEM_BYTES>>>(x, off, axis, out_pos, out_rot, out_gpos);
    const int rem = G - full_blocks * GPB;
    if (rem > 0) {
        const int tb = 128;
        fk_tail_kernel<<<(rem + tb - 1) / tb, tb>>>(x, off, axis, out_pos, out_rot, out_gpos,
                                                    full_blocks * GPB, G);
    }
}